// round 2
// baseline (speedup 1.0000x reference)
#include <cuda_runtime.h>
#include <math.h>

#define BQ 8
#define CC 1024
#define DD 512
#define MROWS 32768            // B*N = 16*2048
#define EPSF 1e-6f

typedef unsigned long long ull;

// ---- scratch (device globals; no allocation allowed) ----
__device__ float g_residual[(size_t)MROWS * DD];   // 64 MB
__device__ float g_cbsq[BQ * CC];
__device__ int   g_idx[MROWS];
__device__ float g_loss[BQ];

// ---- packed f32x2 helpers (sm_103a FFMA2 path, not emitted by ptxas) ----
__device__ __forceinline__ ull pk2(float x) {
    ull r; asm("mov.b64 %0, {%1, %1};" : "=l"(r) : "f"(x)); return r;
}
__device__ __forceinline__ void fma2(ull& d, ull a, ull b) {
    asm("fma.rn.f32x2 %0, %1, %2, %0;" : "+l"(d) : "l"(a), "l"(b));
}
__device__ __forceinline__ float2 upk(ull v) {
    float2 f; asm("mov.b64 {%0, %1}, %2;" : "=f"(f.x), "=f"(f.y) : "l"(v)); return f;
}

// ---------------------------------------------------------------------------
// init: residual = x, zero quantized output section, zero losses
// ---------------------------------------------------------------------------
__global__ void init_kernel(const float* __restrict__ x, float* __restrict__ out_q) {
    size_t i  = (size_t)blockIdx.x * blockDim.x + threadIdx.x;
    size_t n4 = (size_t)MROWS * DD / 4;
    const float4* x4 = (const float4*)x;
    float4* r4 = (float4*)g_residual;
    float4* o4 = (float4*)out_q;
    float4 z = make_float4(0.f, 0.f, 0.f, 0.f);
    for (size_t k = i; k < n4; k += (size_t)gridDim.x * blockDim.x) {
        r4[k] = x4[k];
        o4[k] = z;
    }
    if (i < BQ) g_loss[i] = 0.f;
}

// ---------------------------------------------------------------------------
// cb_sq[q][c] = sum_d codebooks[q][c][d]^2   (one warp per codebook row)
// ---------------------------------------------------------------------------
__global__ void cbsq_kernel(const float* __restrict__ cb) {
    int row  = blockIdx.x * 8 + (threadIdx.x >> 5);   // 0 .. BQ*CC-1
    int lane = threadIdx.x & 31;
    const float4* p = (const float4*)(cb + (size_t)row * DD);
    float s = 0.f;
#pragma unroll
    for (int j = 0; j < 4; j++) {
        float4 v = p[lane + 32 * j];
        s += v.x * v.x + v.y * v.y + v.z * v.z + v.w * v.w;
    }
#pragma unroll
    for (int o = 16; o; o >>= 1) s += __shfl_xor_sync(0xFFFFFFFFu, s, o);
    if (lane == 0) g_cbsq[row] = s;
}

// ---------------------------------------------------------------------------
// Fused distance GEMM + argmin using packed fma.rn.f32x2 (FFMA2).
// BM=128 rows x BN=128 codes per pass, 8x8 per thread (accs paired over j),
// register-prefetch pipeline on the global->smem tile loads.
// ---------------------------------------------------------------------------
#define BM 128
#define BNC 128
#define BK 16
#define TM 8
#define TN 8
#define KT (DD / BK)

__global__ __launch_bounds__(256) void dist_argmin_kernel(
    const float* __restrict__ cbs, int qi)
{
    __shared__ float As[BK][BM];
    __shared__ float Bs[BK][BNC];
    __shared__ float redV[16][BM];
    __shared__ int   redI[16][BM];

    const float* CB  = cbs + (size_t)qi * CC * DD;
    const float* csq = g_cbsq + qi * CC;

    const int tid = threadIdx.x;
    const int tx  = tid & 15;       // code dimension
    const int ty  = tid >> 4;       // row dimension
    const int rowBase = blockIdx.x * BM;

    // per-thread global load coordinates (2 float4 each for A and B per k-tile)
    int lr[2], lk[2];
#pragma unroll
    for (int j = 0; j < 2; j++) {
        int lin = tid + j * 256;          // 0..511
        lr[j] = lin >> 2;                 // 0..127
        lk[j] = (lin & 3) * 4;            // 0,4,8,12
    }

    float best[TM];
    int   bestI[TM];
#pragma unroll
    for (int i = 0; i < TM; i++) { best[i] = INFINITY; bestI[i] = 0x7fffffff; }

    for (int cc = 0; cc < CC / BNC; cc++) {
        ull acc[TM][TN / 2];
#pragma unroll
        for (int i = 0; i < TM; i++)
#pragma unroll
            for (int j = 0; j < TN / 2; j++) acc[i][j] = 0ull;

        // prefetch tile kt=0 into registers
        float4 pa[2], pb[2];
#pragma unroll
        for (int j = 0; j < 2; j++) {
            pa[j] = *(const float4*)(g_residual + (size_t)(rowBase + lr[j]) * DD + lk[j]);
            pb[j] = *(const float4*)(CB + (size_t)(cc * BNC + lr[j]) * DD + lk[j]);
        }

        for (int kt = 0; kt < KT; kt++) {
            // store prefetched tile to smem (transposed)
#pragma unroll
            for (int j = 0; j < 2; j++) {
                As[lk[j] + 0][lr[j]] = pa[j].x; As[lk[j] + 1][lr[j]] = pa[j].y;
                As[lk[j] + 2][lr[j]] = pa[j].z; As[lk[j] + 3][lr[j]] = pa[j].w;
                Bs[lk[j] + 0][lr[j]] = pb[j].x; Bs[lk[j] + 1][lr[j]] = pb[j].y;
                Bs[lk[j] + 2][lr[j]] = pb[j].z; Bs[lk[j] + 3][lr[j]] = pb[j].w;
            }
            __syncthreads();

            // prefetch next tile
            if (kt + 1 < KT) {
                int ko = (kt + 1) * BK;
#pragma unroll
                for (int j = 0; j < 2; j++) {
                    pa[j] = *(const float4*)(g_residual + (size_t)(rowBase + lr[j]) * DD + ko + lk[j]);
                    pb[j] = *(const float4*)(CB + (size_t)(cc * BNC + lr[j]) * DD + ko + lk[j]);
                }
            }

#pragma unroll
            for (int k = 0; k < BK; k++) {
                float4 t0 = *(const float4*)&As[k][ty * TM];
                float4 t1 = *(const float4*)&As[k][ty * TM + 4];
                ull aa[TM];
                aa[0] = pk2(t0.x); aa[1] = pk2(t0.y); aa[2] = pk2(t0.z); aa[3] = pk2(t0.w);
                aa[4] = pk2(t1.x); aa[5] = pk2(t1.y); aa[6] = pk2(t1.z); aa[7] = pk2(t1.w);
                // B pairs read as aligned 64-bit words straight from smem
                ulonglong2 b0 = *(const ulonglong2*)&Bs[k][tx * TN];
                ulonglong2 b1 = *(const ulonglong2*)&Bs[k][tx * TN + 4];
                ull bb[4]; bb[0] = b0.x; bb[1] = b0.y; bb[2] = b1.x; bb[3] = b1.y;
#pragma unroll
                for (int i = 0; i < TM; i++) {
#pragma unroll
                    for (int j = 0; j < TN / 2; j++)
                        fma2(acc[i][j], aa[i], bb[j]);
                }
            }
            __syncthreads();
        }

        // fold this code chunk into running argmin
#pragma unroll
        for (int j = 0; j < TN / 2; j++) {
            int code = cc * BNC + tx * TN + 2 * j;
            float cq0 = csq[code];
            float cq1 = csq[code + 1];
#pragma unroll
            for (int i = 0; i < TM; i++) {
                float2 d = upk(acc[i][j]);
                float v0 = cq0 - 2.f * d.x;
                float v1 = cq1 - 2.f * d.y;
                if (v0 < best[i] || (v0 == best[i] && code < bestI[i])) {
                    best[i] = v0; bestI[i] = code;
                }
                if (v1 < best[i] || (v1 == best[i] && (code + 1) < bestI[i])) {
                    best[i] = v1; bestI[i] = code + 1;
                }
            }
        }
    }

    // cross-thread reduction over the 16 tx slots sharing each row
#pragma unroll
    for (int i = 0; i < TM; i++) {
        redV[tx][ty * TM + i] = best[i];
        redI[tx][ty * TM + i] = bestI[i];
    }
    __syncthreads();
    if (tid < BM) {
        float bv = INFINITY; int bi = 0x7fffffff;
#pragma unroll
        for (int t = 0; t < 16; t++) {
            float v = redV[t][tid];
            int   id = redI[t][tid];
            if (v < bv || (v == bv && id < bi)) { bv = v; bi = id; }
        }
        g_idx[rowBase + tid] = bi;
    }
}

// ---------------------------------------------------------------------------
// Rotation trick + residual/output update + loss + index write. Warp per row.
// ---------------------------------------------------------------------------
__global__ void rotate_kernel(const float* __restrict__ cbs, int qi,
                              float* __restrict__ out_q,
                              float* __restrict__ out_if,
                              int writeIdx, int writeLoss)
{
    __shared__ float ws[8];
    int row  = blockIdx.x * 8 + (threadIdx.x >> 5);
    int lane = threadIdx.x & 31;
    float* zp = g_residual + (size_t)row * DD;
    int idx = g_idx[row];
    const float* qp = cbs + ((size_t)qi * CC + idx) * DD;

    float4 zv[4], qv[4];
    float zz = 0.f, qq = 0.f, zq = 0.f, ll = 0.f;
#pragma unroll
    for (int j = 0; j < 4; j++) {
        zv[j] = ((const float4*)zp)[lane + 32 * j];
        qv[j] = ((const float4*)qp)[lane + 32 * j];
        zz += zv[j].x*zv[j].x + zv[j].y*zv[j].y + zv[j].z*zv[j].z + zv[j].w*zv[j].w;
        qq += qv[j].x*qv[j].x + qv[j].y*qv[j].y + qv[j].z*qv[j].z + qv[j].w*qv[j].w;
        zq += zv[j].x*qv[j].x + zv[j].y*qv[j].y + zv[j].z*qv[j].z + zv[j].w*qv[j].w;
        float dx = qv[j].x - zv[j].x, dy = qv[j].y - zv[j].y;
        float dz = qv[j].z - zv[j].z, dw = qv[j].w - zv[j].w;
        ll += dx*dx + dy*dy + dz*dz + dw*dw;
    }
#pragma unroll
    for (int o = 16; o; o >>= 1) {
        zz += __shfl_xor_sync(0xFFFFFFFFu, zz, o);
        qq += __shfl_xor_sync(0xFFFFFFFFu, qq, o);
        zq += __shfl_xor_sync(0xFFFFFFFFu, zq, o);
        ll += __shfl_xor_sync(0xFFFFFFFFu, ll, o);
    }

    float nz = sqrtf(zz), nq = sqrtf(qq);
    float iz = 1.f / (nz + EPSF), iq = 1.f / (nq + EPSF);
    float s2 = zz * iz * iz + 2.f * zq * iz * iq + qq * iq * iq;
    float A2 = 2.f * (zz * iz + zq * iq) / s2;
    float Bc = 2.f * zz * iz * iq;
    float cz = 1.f - A2 * iz;     // coefficient on z
    float cq = Bc - A2 * iq;      // coefficient on q
    float sc = nq * iz;           // scale

    float* op = out_q + (size_t)row * DD;
#pragma unroll
    for (int j = 0; j < 4; j++) {
        float4 z = zv[j], q = qv[j], t, r, o;
        t.x = (z.x * cz + q.x * cq) * sc;
        t.y = (z.y * cz + q.y * cq) * sc;
        t.z = (z.z * cz + q.z * cq) * sc;
        t.w = (z.w * cz + q.w * cq) * sc;
        r.x = z.x - t.x; r.y = z.y - t.y; r.z = z.z - t.z; r.w = z.w - t.w;
        ((float4*)zp)[lane + 32 * j] = r;
        o = ((float4*)op)[lane + 32 * j];
        o.x += t.x; o.y += t.y; o.z += t.z; o.w += t.w;
        ((float4*)op)[lane + 32 * j] = o;
    }

    if (writeIdx && lane == 0)
        out_if[(size_t)row * BQ + qi] = (float)idx;

    if (writeLoss) {
        if (lane == 0) ws[threadIdx.x >> 5] = ll;
        __syncthreads();
        if (threadIdx.x == 0) {
            float s = 0.f;
#pragma unroll
            for (int w = 0; w < 8; w++) s += ws[w];
            atomicAdd(&g_loss[qi], s);
        }
    }
}

// ---------------------------------------------------------------------------
// finalize: losses = sum / (M*D)
// ---------------------------------------------------------------------------
__global__ void final_kernel(float* __restrict__ out_loss) {
    int i = threadIdx.x;
    if (i < BQ) out_loss[i] = g_loss[i] / (float)((size_t)MROWS * DD);
}

// ---------------------------------------------------------------------------
extern "C" void kernel_launch(void* const* d_in, const int* in_sizes, int n_in,
                              void* d_out, int out_size) {
    const float* x   = (const float*)d_in[0];
    const float* cbs = (const float*)d_in[1];
    // robustness: swap if input order differs
    if (n_in >= 2 && in_sizes[0] == BQ * CC * DD && in_sizes[1] == MROWS * DD) {
        const float* t = x; x = cbs; cbs = t;
    }

    float* out = (float*)d_out;
    const long long qElems = (long long)MROWS * DD;   // 16777216
    const long long iElems = (long long)MROWS * BQ;   // 262144
    float* out_q = out;
    float* out_i = out + qElems;
    float* out_l = out + qElems + iElems;
    int haveIdx  = (out_size >= qElems + iElems) ? 1 : 0;
    int haveLoss = (out_size >= qElems + iElems + BQ) ? 1 : 0;

    init_kernel<<<1024, 256>>>(x, out_q);
    cbsq_kernel<<<BQ * CC / 8, 256>>>(cbs);

    for (int qi = 0; qi < BQ; qi++) {
        dist_argmin_kernel<<<MROWS / BM, 256>>>(cbs, qi);
        rotate_kernel<<<MROWS / 8, 256>>>(cbs, qi, out_q, out_i, haveIdx, haveLoss);
    }

    if (haveLoss) final_kernel<<<1, 32>>>(out_l);
}

// round 4
// speedup vs baseline: 1.7964x; 1.7964x over previous
#include <cuda_runtime.h>
#include <cuda_bf16.h>
#include <math.h>
#include <stdint.h>

#define BQ 8
#define CC 1024
#define DD 512
#define MROWS 32768            // B*N = 16*2048
#define EPSF 1e-6f

// ---- scratch (device globals; no allocation allowed) ----
__device__ float g_residual[(size_t)MROWS * DD];   // 64 MB fp32 residual
__device__ uint4 g_res_h4[(size_t)MROWS * 64];     // 32 MB bf16 hi  [row][512]
__device__ uint4 g_res_l4[(size_t)MROWS * 64];     // 32 MB bf16 lo
__device__ uint4 g_cb_h4[(size_t)BQ * CC * 64];    // 8 MB bf16 hi codebooks
__device__ uint4 g_cb_l4[(size_t)BQ * CC * 64];    // 8 MB bf16 lo
__device__ float g_cbsq[BQ * CC];
__device__ int   g_idx[MROWS];
__device__ float g_loss[BQ];

// ============================================================================
// portable PTX helpers (sm_80-level: cp.async, ldmatrix, mma.sync — no 'a' feats)
// ============================================================================
__device__ __forceinline__ uint32_t smem_to_u32(const void* p) {
    uint32_t a;
    asm("{ .reg .u64 t; cvta.to.shared.u64 t, %1; cvt.u32.u64 %0, t; }"
        : "=r"(a) : "l"(p));
    return a;
}
__device__ __forceinline__ void cpasync16(uint32_t dst, const void* src) {
    asm volatile("cp.async.cg.shared.global [%0], [%1], 16;" :: "r"(dst), "l"(src));
}
#define CP_COMMIT() asm volatile("cp.async.commit_group;" ::: "memory")
#define CP_WAIT(n)  asm volatile("cp.async.wait_group %0;" :: "n"(n) : "memory")

__device__ __forceinline__ void ldsm4(uint32_t& r0, uint32_t& r1, uint32_t& r2,
                                      uint32_t& r3, uint32_t addr) {
    asm volatile("ldmatrix.sync.aligned.m8n8.x4.shared.b16 {%0,%1,%2,%3}, [%4];"
                 : "=r"(r0), "=r"(r1), "=r"(r2), "=r"(r3) : "r"(addr));
}
__device__ __forceinline__ void mma16816(float* c, uint32_t a0, uint32_t a1,
                                         uint32_t a2, uint32_t a3,
                                         uint32_t b0, uint32_t b1) {
    asm volatile(
        "mma.sync.aligned.m16n8k16.row.col.f32.bf16.bf16.f32 "
        "{%0,%1,%2,%3}, {%4,%5,%6,%7}, {%8,%9}, {%0,%1,%2,%3};"
        : "+f"(c[0]), "+f"(c[1]), "+f"(c[2]), "+f"(c[3])
        : "r"(a0), "r"(a1), "r"(a2), "r"(a3), "r"(b0), "r"(b1));
}

// ---- bf16 split helper ----
__device__ __forceinline__ void split4(float4 v, ushort4& h, ushort4& l) {
    __nv_bfloat16 hx = __float2bfloat16_rn(v.x);
    __nv_bfloat16 hy = __float2bfloat16_rn(v.y);
    __nv_bfloat16 hz = __float2bfloat16_rn(v.z);
    __nv_bfloat16 hw = __float2bfloat16_rn(v.w);
    h.x = __bfloat16_as_ushort(hx); h.y = __bfloat16_as_ushort(hy);
    h.z = __bfloat16_as_ushort(hz); h.w = __bfloat16_as_ushort(hw);
    l.x = __bfloat16_as_ushort(__float2bfloat16_rn(v.x - __bfloat162float(hx)));
    l.y = __bfloat16_as_ushort(__float2bfloat16_rn(v.y - __bfloat162float(hy)));
    l.z = __bfloat16_as_ushort(__float2bfloat16_rn(v.z - __bfloat162float(hz)));
    l.w = __bfloat16_as_ushort(__float2bfloat16_rn(v.w - __bfloat162float(hw)));
}

// ---------------------------------------------------------------------------
// init: residual = x (fp32 + bf16 hi/lo), zero out_q section, zero losses
// ---------------------------------------------------------------------------
__global__ void init_kernel(const float* __restrict__ x, float* __restrict__ out_q) {
    size_t i  = (size_t)blockIdx.x * blockDim.x + threadIdx.x;
    size_t n4 = (size_t)MROWS * DD / 4;
    const float4* x4 = (const float4*)x;
    float4* r4 = (float4*)g_residual;
    float4* o4 = (float4*)out_q;
    ushort4* rh = (ushort4*)g_res_h4;
    ushort4* rl = (ushort4*)g_res_l4;
    float4 z = make_float4(0.f, 0.f, 0.f, 0.f);
    for (size_t k = i; k < n4; k += (size_t)gridDim.x * blockDim.x) {
        float4 v = x4[k];
        r4[k] = v;
        o4[k] = z;
        ushort4 h, l; split4(v, h, l);
        rh[k] = h; rl[k] = l;
    }
    if (i < BQ) g_loss[i] = 0.f;
}

// ---------------------------------------------------------------------------
// codebook: cb_sq + bf16 hi/lo conversion
// ---------------------------------------------------------------------------
__global__ void cbsq_kernel(const float* __restrict__ cb) {
    int row  = blockIdx.x * 8 + (threadIdx.x >> 5);   // 0 .. BQ*CC-1
    int lane = threadIdx.x & 31;
    const float4* p = (const float4*)(cb + (size_t)row * DD);
    ushort4* ch = (ushort4*)g_cb_h4;
    ushort4* cl = (ushort4*)g_cb_l4;
    float s = 0.f;
#pragma unroll
    for (int j = 0; j < 4; j++) {
        float4 v = p[lane + 32 * j];
        s += v.x * v.x + v.y * v.y + v.z * v.z + v.w * v.w;
        ushort4 h, l; split4(v, h, l);
        size_t q = (size_t)row * 128 + lane + 32 * j;
        ch[q] = h; cl[q] = l;
    }
#pragma unroll
    for (int o = 16; o; o >>= 1) s += __shfl_xor_sync(0xFFFFFFFFu, s, o);
    if (lane == 0) g_cbsq[row] = s;
}

// ---------------------------------------------------------------------------
// mma.sync distance GEMM + argmin.
// Logical K = 2048 bf16 (4 segments: Ah.Bh, Al.Bh, Ah.Bl, Al.Bl — exact fp32
// recovery). CTA tile 128 rows x 128 codes, 8 N-tiles per CTA (all 1024 codes).
// 4-stage cp.async pipeline, KC = 32 bf16 per chunk, smem pitch 80B
// (bank-conflict-free ldmatrix, 16B-aligned cp.async).
// ---------------------------------------------------------------------------
#define PITCH   80
#define TILEB   (128 * PITCH)          // 10240 per operand
#define STAGEB  (2 * TILEB)            // 20480 A+B
#define NSTAGE  4
#define SMEM_DYN (NSTAGE * STAGEB)     // 81920

__device__ __forceinline__ void issue_chunk(
    uint32_t sb, int rowBase, int qi, int nt, int kc, int stage)
{
    int seg  = kc >> 4;                 // 0..3
    int koff = (kc & 15) * 64;          // byte offset within 1024B row
    const char* Ab = (const char*)((seg & 1) ? g_res_l4 : g_res_h4);
    const char* Bb = (const char*)((seg >> 1) ? g_cb_l4 : g_cb_h4);
    uint32_t base = sb + stage * STAGEB;
    int tid = threadIdx.x;
    size_t bRow = (size_t)(qi * CC + nt * 128);
#pragma unroll
    for (int i = 0; i < 2; i++) {
        int g = tid + 256 * i;          // 0..511
        int r = g >> 2, c = g & 3;
        uint32_t da = base + r * PITCH + c * 16;
        cpasync16(da, Ab + (size_t)(rowBase + r) * 1024 + koff + c * 16);
        uint32_t db = base + TILEB + r * PITCH + c * 16;
        cpasync16(db, Bb + (bRow + r) * 1024 + koff + c * 16);
    }
}

__global__ __launch_bounds__(256, 2) void dist_mma_kernel(int qi)
{
    extern __shared__ char smem[];
    __shared__ float redV[2][128];
    __shared__ int   redI[2][128];
    uint32_t sb = smem_to_u32(smem);

    const int tid  = threadIdx.x;
    const int wid  = tid >> 5;
    const int lane = tid & 31;
    const int rowBase = blockIdx.x * 128;
    const int wM = (wid & 3) * 32;      // warp row offset in tile
    const int wN = (wid >> 2) * 64;     // warp col offset in tile

    // ldmatrix per-lane offsets (within a stage buffer)
    const int aRow = lane & 15;
    const int aCol = (lane >> 4) * 16;
    const int bRowL = (lane & 7) + ((lane >> 4) << 3);
    const int bColL = ((lane >> 3) & 1) * 16;
    const uint32_t aOffBase = (uint32_t)((wM + aRow) * PITCH + aCol);
    const uint32_t bOffBase = (uint32_t)(TILEB + (wN + bRowL) * PITCH + bColL);

    const float2* csq2 = (const float2*)(g_cbsq + qi * CC);

    float best[4];
    int   bestI[4];
#pragma unroll
    for (int s = 0; s < 4; s++) { best[s] = INFINITY; bestI[s] = 0x7fffffff; }

#pragma unroll 1
    for (int nt = 0; nt < 8; nt++) {
        float acc[2][8][4];
#pragma unroll
        for (int mf = 0; mf < 2; mf++)
#pragma unroll
            for (int nf = 0; nf < 8; nf++)
#pragma unroll
                for (int e = 0; e < 4; e++) acc[mf][nf][e] = 0.f;

        // pipeline prologue: stages 0,1,2
        issue_chunk(sb, rowBase, qi, nt, 0, 0); CP_COMMIT();
        issue_chunk(sb, rowBase, qi, nt, 1, 1); CP_COMMIT();
        issue_chunk(sb, rowBase, qi, nt, 2, 2); CP_COMMIT();

#pragma unroll 1
        for (int kc = 0; kc < 64; kc++) {
            if (kc < 62) { CP_WAIT(2); } else if (kc == 62) { CP_WAIT(1); }
            else { CP_WAIT(0); }
            __syncthreads();
            if (kc + 3 < 64) {
                issue_chunk(sb, rowBase, qi, nt, kc + 3, (kc + 3) & 3);
                CP_COMMIT();
            }

            uint32_t stageBase = sb + (kc & 3) * STAGEB;
#pragma unroll
            for (int k16 = 0; k16 < 2; k16++) {
                uint32_t a[2][4];
#pragma unroll
                for (int mf = 0; mf < 2; mf++)
                    ldsm4(a[mf][0], a[mf][1], a[mf][2], a[mf][3],
                          stageBase + aOffBase + mf * 16 * PITCH + k16 * 32);
#pragma unroll
                for (int np = 0; np < 4; np++) {
                    uint32_t b0, b1, b2, b3;
                    ldsm4(b0, b1, b2, b3,
                          stageBase + bOffBase + np * 16 * PITCH + k16 * 32);
#pragma unroll
                    for (int mf = 0; mf < 2; mf++) {
                        mma16816(acc[mf][np * 2],
                                 a[mf][0], a[mf][1], a[mf][2], a[mf][3], b0, b1);
                        mma16816(acc[mf][np * 2 + 1],
                                 a[mf][0], a[mf][1], a[mf][2], a[mf][3], b2, b3);
                    }
                }
            }
        }
        __syncthreads();   // drain before next nt reuses stage buffers

        // fold accumulators: v = csq[n] - 2*dot; first-min tie-break
#pragma unroll
        for (int mf = 0; mf < 2; mf++) {
#pragma unroll
            for (int nf = 0; nf < 8; nf++) {
                int n = nt * 128 + wN + nf * 8 + (lane & 3) * 2;
                float2 cq = csq2[n >> 1];
                float v0 = cq.x - 2.f * acc[mf][nf][0];
                float v1 = cq.y - 2.f * acc[mf][nf][1];
                float v2 = cq.x - 2.f * acc[mf][nf][2];
                float v3 = cq.y - 2.f * acc[mf][nf][3];
                int s0 = mf * 2, s1 = mf * 2 + 1;
                if (v0 < best[s0] || (v0 == best[s0] && n < bestI[s0]))
                    { best[s0] = v0; bestI[s0] = n; }
                if (v1 < best[s0] || (v1 == best[s0] && n + 1 < bestI[s0]))
                    { best[s0] = v1; bestI[s0] = n + 1; }
                if (v2 < best[s1] || (v2 == best[s1] && n < bestI[s1]))
                    { best[s1] = v2; bestI[s1] = n; }
                if (v3 < best[s1] || (v3 == best[s1] && n + 1 < bestI[s1]))
                    { best[s1] = v3; bestI[s1] = n + 1; }
            }
        }
    }

    // reduce across the 4 lanes sharing each row (lane & 3)
#pragma unroll
    for (int s = 0; s < 4; s++) {
#pragma unroll
        for (int o = 1; o <= 2; o <<= 1) {
            float ov = __shfl_xor_sync(0xFFFFFFFFu, best[s], o);
            int   oi = __shfl_xor_sync(0xFFFFFFFFu, bestI[s], o);
            if (ov < best[s] || (ov == best[s] && oi < bestI[s]))
                { best[s] = ov; bestI[s] = oi; }
        }
    }
    if ((lane & 3) == 0) {
        int wg = wid >> 2;
#pragma unroll
        for (int s = 0; s < 4; s++) {
            // s = mf*2+h -> row offset mf*16 + h*8
            int rloc = wM + ((s >> 1) * 16) + ((s & 1) * 8) + (lane >> 2);
            redV[wg][rloc] = best[s];
            redI[wg][rloc] = bestI[s];
        }
    }
    __syncthreads();
    if (tid < 128) {
        float v0 = redV[0][tid]; int i0 = redI[0][tid];
        float v1 = redV[1][tid]; int i1 = redI[1][tid];
        if (v1 < v0 || (v1 == v0 && i1 < i0)) { v0 = v1; i0 = i1; }
        g_idx[rowBase + tid] = i0;
    }
}

// ---------------------------------------------------------------------------
// Rotation trick + residual/output update + loss + index write + bf16 split
// of the new residual (for the next stage's MMA). Warp per row.
// ---------------------------------------------------------------------------
__global__ void rotate_kernel(const float* __restrict__ cbs, int qi,
                              float* __restrict__ out_q,
                              float* __restrict__ out_if,
                              int writeIdx, int writeLoss, int writeConv)
{
    __shared__ float ws[8];
    int row  = blockIdx.x * 8 + (threadIdx.x >> 5);
    int lane = threadIdx.x & 31;
    float* zp = g_residual + (size_t)row * DD;
    int idx = g_idx[row];
    const float* qp = cbs + ((size_t)qi * CC + idx) * DD;

    float4 zv[4], qv[4];
    float zz = 0.f, qq = 0.f, zq = 0.f, ll = 0.f;
#pragma unroll
    for (int j = 0; j < 4; j++) {
        zv[j] = ((const float4*)zp)[lane + 32 * j];
        qv[j] = ((const float4*)qp)[lane + 32 * j];
        zz += zv[j].x*zv[j].x + zv[j].y*zv[j].y + zv[j].z*zv[j].z + zv[j].w*zv[j].w;
        qq += qv[j].x*qv[j].x + qv[j].y*qv[j].y + qv[j].z*qv[j].z + qv[j].w*qv[j].w;
        zq += zv[j].x*qv[j].x + zv[j].y*qv[j].y + zv[j].z*qv[j].z + zv[j].w*qv[j].w;
        float dx = qv[j].x - zv[j].x, dy = qv[j].y - zv[j].y;
        float dz = qv[j].z - zv[j].z, dw = qv[j].w - zv[j].w;
        ll += dx*dx + dy*dy + dz*dz + dw*dw;
    }
#pragma unroll
    for (int o = 16; o; o >>= 1) {
        zz += __shfl_xor_sync(0xFFFFFFFFu, zz, o);
        qq += __shfl_xor_sync(0xFFFFFFFFu, qq, o);
        zq += __shfl_xor_sync(0xFFFFFFFFu, zq, o);
        ll += __shfl_xor_sync(0xFFFFFFFFu, ll, o);
    }

    float nz = sqrtf(zz), nq = sqrtf(qq);
    float iz = 1.f / (nz + EPSF), iq = 1.f / (nq + EPSF);
    float s2 = zz * iz * iz + 2.f * zq * iz * iq + qq * iq * iq;
    float A2 = 2.f * (zz * iz + zq * iq) / s2;
    float Bc = 2.f * zz * iz * iq;
    float cz = 1.f - A2 * iz;
    float cq = Bc - A2 * iq;
    float sc = nq * iz;

    float* op = out_q + (size_t)row * DD;
    ushort4* rh = (ushort4*)g_res_h4;
    ushort4* rl = (ushort4*)g_res_l4;
#pragma unroll
    for (int j = 0; j < 4; j++) {
        float4 z = zv[j], q = qv[j], t, r, o;
        t.x = (z.x * cz + q.x * cq) * sc;
        t.y = (z.y * cz + q.y * cq) * sc;
        t.z = (z.z * cz + q.z * cq) * sc;
        t.w = (z.w * cz + q.w * cq) * sc;
        r.x = z.x - t.x; r.y = z.y - t.y; r.z = z.z - t.z; r.w = z.w - t.w;
        ((float4*)zp)[lane + 32 * j] = r;
        o = ((float4*)op)[lane + 32 * j];
        o.x += t.x; o.y += t.y; o.z += t.z; o.w += t.w;
        ((float4*)op)[lane + 32 * j] = o;
        if (writeConv) {
            ushort4 h, l; split4(r, h, l);
            size_t e = (size_t)row * 128 + lane + 32 * j;
            rh[e] = h; rl[e] = l;
        }
    }

    if (writeIdx && lane == 0)
        out_if[(size_t)row * BQ + qi] = (float)idx;

    if (writeLoss) {
        if (lane == 0) ws[threadIdx.x >> 5] = ll;
        __syncthreads();
        if (threadIdx.x == 0) {
            float s = 0.f;
#pragma unroll
            for (int w = 0; w < 8; w++) s += ws[w];
            atomicAdd(&g_loss[qi], s);
        }
    }
}

// ---------------------------------------------------------------------------
__global__ void final_kernel(float* __restrict__ out_loss) {
    int i = threadIdx.x;
    if (i < BQ) out_loss[i] = g_loss[i] / (float)((size_t)MROWS * DD);
}

// ---------------------------------------------------------------------------
extern "C" void kernel_launch(void* const* d_in, const int* in_sizes, int n_in,
                              void* d_out, int out_size) {
    const float* x   = (const float*)d_in[0];
    const float* cbs = (const float*)d_in[1];
    if (n_in >= 2 && in_sizes[0] == BQ * CC * DD && in_sizes[1] == MROWS * DD) {
        const float* t = x; x = cbs; cbs = t;
    }

    float* out = (float*)d_out;
    const long long qElems = (long long)MROWS * DD;   // 16777216
    const long long iElems = (long long)MROWS * BQ;   // 262144
    float* out_q = out;
    float* out_i = out + qElems;
    float* out_l = out + qElems + iElems;
    int haveIdx  = (out_size >= qElems + iElems) ? 1 : 0;
    int haveLoss = (out_size >= qElems + iElems + BQ) ? 1 : 0;

    static int attrSet = 0;
    if (!attrSet) {
        cudaFuncSetAttribute(dist_mma_kernel,
                             cudaFuncAttributeMaxDynamicSharedMemorySize, SMEM_DYN);
        attrSet = 1;
    }

    init_kernel<<<1024, 256>>>(x, out_q);
    cbsq_kernel<<<BQ * CC / 8, 256>>>(cbs);

    for (int qi = 0; qi < BQ; qi++) {
        dist_mma_kernel<<<MROWS / 128, 256, SMEM_DYN>>>(qi);
        rotate_kernel<<<MROWS / 8, 256>>>(cbs, qi, out_q, out_i,
                                          haveIdx, haveLoss, qi < BQ - 1);
    }

    if (haveLoss) final_kernel<<<1, 32>>>(out_l);
}

// round 5
// speedup vs baseline: 2.2946x; 1.2773x over previous
#include <cuda_runtime.h>
#include <cuda_bf16.h>
#include <math.h>
#include <stdint.h>

#define BQ 8
#define CC 1024
#define DD 512
#define MROWS 32768            // B*N = 16*2048
#define EPSF 1e-6f

// ---- scratch (device globals; no allocation allowed) ----
__device__ float g_residual[(size_t)MROWS * DD];   // 64 MB fp32 residual
__device__ uint4 g_res_h4[(size_t)MROWS * 64];     // 32 MB bf16 hi  [row][512]
__device__ uint4 g_res_l4[(size_t)MROWS * 64];     // 32 MB bf16 lo
__device__ uint4 g_cb_h4[(size_t)BQ * CC * 64];    // 8 MB bf16 hi codebooks
__device__ uint4 g_cb_l4[(size_t)BQ * CC * 64];    // 8 MB bf16 lo
__device__ float g_cbsq[BQ * CC];
__device__ int   g_idx[MROWS];
__device__ float g_loss[BQ];

// ============================================================================
// portable PTX helpers (sm_80-level: cp.async, ldmatrix, mma.sync — no 'a' feats)
// ============================================================================
__device__ __forceinline__ uint32_t smem_to_u32(const void* p) {
    uint32_t a;
    asm("{ .reg .u64 t; cvta.to.shared.u64 t, %1; cvt.u32.u64 %0, t; }"
        : "=r"(a) : "l"(p));
    return a;
}
__device__ __forceinline__ void cpasync16(uint32_t dst, const void* src) {
    asm volatile("cp.async.cg.shared.global [%0], [%1], 16;" :: "r"(dst), "l"(src));
}
#define CP_COMMIT() asm volatile("cp.async.commit_group;" ::: "memory")
#define CP_WAIT(n)  asm volatile("cp.async.wait_group %0;" :: "n"(n) : "memory")

__device__ __forceinline__ void ldsm4(uint32_t& r0, uint32_t& r1, uint32_t& r2,
                                      uint32_t& r3, uint32_t addr) {
    asm volatile("ldmatrix.sync.aligned.m8n8.x4.shared.b16 {%0,%1,%2,%3}, [%4];"
                 : "=r"(r0), "=r"(r1), "=r"(r2), "=r"(r3) : "r"(addr));
}
__device__ __forceinline__ void mma16816(float* c, uint32_t a0, uint32_t a1,
                                         uint32_t a2, uint32_t a3,
                                         uint32_t b0, uint32_t b1) {
    asm volatile(
        "mma.sync.aligned.m16n8k16.row.col.f32.bf16.bf16.f32 "
        "{%0,%1,%2,%3}, {%4,%5,%6,%7}, {%8,%9}, {%0,%1,%2,%3};"
        : "+f"(c[0]), "+f"(c[1]), "+f"(c[2]), "+f"(c[3])
        : "r"(a0), "r"(a1), "r"(a2), "r"(a3), "r"(b0), "r"(b1));
}

// ---- bf16 split helper ----
__device__ __forceinline__ void split4(float4 v, ushort4& h, ushort4& l) {
    __nv_bfloat16 hx = __float2bfloat16_rn(v.x);
    __nv_bfloat16 hy = __float2bfloat16_rn(v.y);
    __nv_bfloat16 hz = __float2bfloat16_rn(v.z);
    __nv_bfloat16 hw = __float2bfloat16_rn(v.w);
    h.x = __bfloat16_as_ushort(hx); h.y = __bfloat16_as_ushort(hy);
    h.z = __bfloat16_as_ushort(hz); h.w = __bfloat16_as_ushort(hw);
    l.x = __bfloat16_as_ushort(__float2bfloat16_rn(v.x - __bfloat162float(hx)));
    l.y = __bfloat16_as_ushort(__float2bfloat16_rn(v.y - __bfloat162float(hy)));
    l.z = __bfloat16_as_ushort(__float2bfloat16_rn(v.z - __bfloat162float(hz)));
    l.w = __bfloat16_as_ushort(__float2bfloat16_rn(v.w - __bfloat162float(hw)));
}

// ---------------------------------------------------------------------------
// init: residual = x (fp32 + bf16 hi/lo), zero out_q section, zero losses
// ---------------------------------------------------------------------------
__global__ void init_kernel(const float* __restrict__ x, float* __restrict__ out_q) {
    size_t i  = (size_t)blockIdx.x * blockDim.x + threadIdx.x;
    size_t n4 = (size_t)MROWS * DD / 4;
    const float4* x4 = (const float4*)x;
    float4* r4 = (float4*)g_residual;
    float4* o4 = (float4*)out_q;
    ushort4* rh = (ushort4*)g_res_h4;
    ushort4* rl = (ushort4*)g_res_l4;
    float4 z = make_float4(0.f, 0.f, 0.f, 0.f);
    for (size_t k = i; k < n4; k += (size_t)gridDim.x * blockDim.x) {
        float4 v = x4[k];
        r4[k] = v;
        o4[k] = z;
        ushort4 h, l; split4(v, h, l);
        rh[k] = h; rl[k] = l;
    }
    if (i < BQ) g_loss[i] = 0.f;
}

// ---------------------------------------------------------------------------
// codebook: cb_sq + bf16 hi/lo conversion
// ---------------------------------------------------------------------------
__global__ void cbsq_kernel(const float* __restrict__ cb) {
    int row  = blockIdx.x * 8 + (threadIdx.x >> 5);   // 0 .. BQ*CC-1
    int lane = threadIdx.x & 31;
    const float4* p = (const float4*)(cb + (size_t)row * DD);
    ushort4* ch = (ushort4*)g_cb_h4;
    ushort4* cl = (ushort4*)g_cb_l4;
    float s = 0.f;
#pragma unroll
    for (int j = 0; j < 4; j++) {
        float4 v = p[lane + 32 * j];
        s += v.x * v.x + v.y * v.y + v.z * v.z + v.w * v.w;
        ushort4 h, l; split4(v, h, l);
        size_t q = (size_t)row * 128 + lane + 32 * j;
        ch[q] = h; cl[q] = l;
    }
#pragma unroll
    for (int o = 16; o; o >>= 1) s += __shfl_xor_sync(0xFFFFFFFFu, s, o);
    if (lane == 0) g_cbsq[row] = s;
}

// ---------------------------------------------------------------------------
// mma.sync distance GEMM + argmin.
// Logical K = 1536 bf16 (3 segments: Ah.Bh, Al.Bh, Ah.Bl — the Al.Bl term is
// ~2^-34 relative and dropped). CTA tile 128 rows x 128 codes, 8 N-tiles per
// CTA (all 1024 codes). 4-stage cp.async pipeline, KC = 32 bf16 per chunk,
// smem pitch 80B (bank-conflict-free ldmatrix, 16B-aligned cp.async).
// ---------------------------------------------------------------------------
#define PITCH   80
#define TILEB   (128 * PITCH)          // 10240 per operand
#define STAGEB  (2 * TILEB)            // 20480 A+B
#define NSTAGE  4
#define NKC     48                     // 3 segments x 16 chunks
#define SMEM_DYN (NSTAGE * STAGEB)     // 81920

__device__ __forceinline__ void issue_chunk(
    uint32_t sb, int rowBase, int qi, int nt, int kc, int stage)
{
    int seg  = kc >> 4;                 // 0: hh, 1: lh, 2: hl
    int koff = (kc & 15) * 64;          // byte offset within 1024B row
    const char* Ab = (const char*)((seg == 1) ? g_res_l4 : g_res_h4);
    const char* Bb = (const char*)((seg == 2) ? g_cb_l4 : g_cb_h4);
    uint32_t base = sb + stage * STAGEB;
    int tid = threadIdx.x;
    size_t bRow = (size_t)(qi * CC + nt * 128);
#pragma unroll
    for (int i = 0; i < 2; i++) {
        int g = tid + 256 * i;          // 0..511
        int r = g >> 2, c = g & 3;
        uint32_t da = base + r * PITCH + c * 16;
        cpasync16(da, Ab + (size_t)(rowBase + r) * 1024 + koff + c * 16);
        uint32_t db = base + TILEB + r * PITCH + c * 16;
        cpasync16(db, Bb + (bRow + r) * 1024 + koff + c * 16);
    }
}

__global__ __launch_bounds__(256, 2) void dist_mma_kernel(int qi)
{
    extern __shared__ char smem[];
    __shared__ float redV[2][128];
    __shared__ int   redI[2][128];
    uint32_t sb = smem_to_u32(smem);

    const int tid  = threadIdx.x;
    const int wid  = tid >> 5;
    const int lane = tid & 31;
    const int rowBase = blockIdx.x * 128;
    const int wM = (wid & 3) * 32;      // warp row offset in tile
    const int wN = (wid >> 2) * 64;     // warp col offset in tile

    // ldmatrix per-lane offsets (within a stage buffer)
    const int aRow = lane & 15;
    const int aCol = (lane >> 4) * 16;
    const int bRowL = (lane & 7) + ((lane >> 4) << 3);
    const int bColL = ((lane >> 3) & 1) * 16;
    const uint32_t aOffBase = (uint32_t)((wM + aRow) * PITCH + aCol);
    const uint32_t bOffBase = (uint32_t)(TILEB + (wN + bRowL) * PITCH + bColL);

    const float2* csq2 = (const float2*)(g_cbsq + qi * CC);

    float best[4];
    int   bestI[4];
#pragma unroll
    for (int s = 0; s < 4; s++) { best[s] = INFINITY; bestI[s] = 0x7fffffff; }

#pragma unroll 1
    for (int nt = 0; nt < 8; nt++) {
        float acc[2][8][4];
#pragma unroll
        for (int mf = 0; mf < 2; mf++)
#pragma unroll
            for (int nf = 0; nf < 8; nf++)
#pragma unroll
                for (int e = 0; e < 4; e++) acc[mf][nf][e] = 0.f;

        // pipeline prologue: stages 0,1,2
        issue_chunk(sb, rowBase, qi, nt, 0, 0); CP_COMMIT();
        issue_chunk(sb, rowBase, qi, nt, 1, 1); CP_COMMIT();
        issue_chunk(sb, rowBase, qi, nt, 2, 2); CP_COMMIT();

#pragma unroll 1
        for (int kc = 0; kc < NKC; kc++) {
            if (kc < NKC - 2) { CP_WAIT(2); } else if (kc == NKC - 2) { CP_WAIT(1); }
            else { CP_WAIT(0); }
            __syncthreads();
            if (kc + 3 < NKC) {
                issue_chunk(sb, rowBase, qi, nt, kc + 3, (kc + 3) & 3);
                CP_COMMIT();
            }

            uint32_t stageBase = sb + (kc & 3) * STAGEB;
#pragma unroll
            for (int k16 = 0; k16 < 2; k16++) {
                uint32_t a[2][4];
#pragma unroll
                for (int mf = 0; mf < 2; mf++)
                    ldsm4(a[mf][0], a[mf][1], a[mf][2], a[mf][3],
                          stageBase + aOffBase + mf * 16 * PITCH + k16 * 32);
#pragma unroll
                for (int np = 0; np < 4; np++) {
                    uint32_t b0, b1, b2, b3;
                    ldsm4(b0, b1, b2, b3,
                          stageBase + bOffBase + np * 16 * PITCH + k16 * 32);
#pragma unroll
                    for (int mf = 0; mf < 2; mf++) {
                        mma16816(acc[mf][np * 2],
                                 a[mf][0], a[mf][1], a[mf][2], a[mf][3], b0, b1);
                        mma16816(acc[mf][np * 2 + 1],
                                 a[mf][0], a[mf][1], a[mf][2], a[mf][3], b2, b3);
                    }
                }
            }
        }
        __syncthreads();   // drain before next nt reuses stage buffers

        // fold accumulators: v = csq[n] - 2*dot; first-min tie-break
#pragma unroll
        for (int mf = 0; mf < 2; mf++) {
#pragma unroll
            for (int nf = 0; nf < 8; nf++) {
                int n = nt * 128 + wN + nf * 8 + (lane & 3) * 2;
                float2 cq = csq2[n >> 1];
                float v0 = cq.x - 2.f * acc[mf][nf][0];
                float v1 = cq.y - 2.f * acc[mf][nf][1];
                float v2 = cq.x - 2.f * acc[mf][nf][2];
                float v3 = cq.y - 2.f * acc[mf][nf][3];
                int s0 = mf * 2, s1 = mf * 2 + 1;
                if (v0 < best[s0] || (v0 == best[s0] && n < bestI[s0]))
                    { best[s0] = v0; bestI[s0] = n; }
                if (v1 < best[s0] || (v1 == best[s0] && n + 1 < bestI[s0]))
                    { best[s0] = v1; bestI[s0] = n + 1; }
                if (v2 < best[s1] || (v2 == best[s1] && n < bestI[s1]))
                    { best[s1] = v2; bestI[s1] = n; }
                if (v3 < best[s1] || (v3 == best[s1] && n + 1 < bestI[s1]))
                    { best[s1] = v3; bestI[s1] = n + 1; }
            }
        }
    }

    // reduce across the 4 lanes sharing each row (lane & 3)
#pragma unroll
    for (int s = 0; s < 4; s++) {
#pragma unroll
        for (int o = 1; o <= 2; o <<= 1) {
            float ov = __shfl_xor_sync(0xFFFFFFFFu, best[s], o);
            int   oi = __shfl_xor_sync(0xFFFFFFFFu, bestI[s], o);
            if (ov < best[s] || (ov == best[s] && oi < bestI[s]))
                { best[s] = ov; bestI[s] = oi; }
        }
    }
    if ((lane & 3) == 0) {
        int wg = wid >> 2;
#pragma unroll
        for (int s = 0; s < 4; s++) {
            // s = mf*2+h -> row offset mf*16 + h*8
            int rloc = wM + ((s >> 1) * 16) + ((s & 1) * 8) + (lane >> 2);
            redV[wg][rloc] = best[s];
            redI[wg][rloc] = bestI[s];
        }
    }
    __syncthreads();
    if (tid < 128) {
        float v0 = redV[0][tid]; int i0 = redI[0][tid];
        float v1 = redV[1][tid]; int i1 = redI[1][tid];
        if (v1 < v0 || (v1 == v0 && i1 < i0)) { v0 = v1; i0 = i1; }
        g_idx[rowBase + tid] = i0;
    }
}

// ---------------------------------------------------------------------------
// Rotation trick + residual/output update + loss + index write + bf16 split
// of the new residual (for the next stage's MMA). Warp per row.
// ---------------------------------------------------------------------------
__global__ void rotate_kernel(const float* __restrict__ cbs, int qi,
                              float* __restrict__ out_q,
                              float* __restrict__ out_if,
                              int writeIdx, int writeLoss, int writeConv)
{
    __shared__ float ws[8];
    int row  = blockIdx.x * 8 + (threadIdx.x >> 5);
    int lane = threadIdx.x & 31;
    float* zp = g_residual + (size_t)row * DD;
    int idx = g_idx[row];
    const float* qp = cbs + ((size_t)qi * CC + idx) * DD;

    float4 zv[4], qv[4];
    float zz = 0.f, qq = 0.f, zq = 0.f, ll = 0.f;
#pragma unroll
    for (int j = 0; j < 4; j++) {
        zv[j] = ((const float4*)zp)[lane + 32 * j];
        qv[j] = ((const float4*)qp)[lane + 32 * j];
        zz += zv[j].x*zv[j].x + zv[j].y*zv[j].y + zv[j].z*zv[j].z + zv[j].w*zv[j].w;
        qq += qv[j].x*qv[j].x + qv[j].y*qv[j].y + qv[j].z*qv[j].z + qv[j].w*qv[j].w;
        zq += zv[j].x*qv[j].x + zv[j].y*qv[j].y + zv[j].z*qv[j].z + zv[j].w*qv[j].w;
        float dx = qv[j].x - zv[j].x, dy = qv[j].y - zv[j].y;
        float dz = qv[j].z - zv[j].z, dw = qv[j].w - zv[j].w;
        ll += dx*dx + dy*dy + dz*dz + dw*dw;
    }
#pragma unroll
    for (int o = 16; o; o >>= 1) {
        zz += __shfl_xor_sync(0xFFFFFFFFu, zz, o);
        qq += __shfl_xor_sync(0xFFFFFFFFu, qq, o);
        zq += __shfl_xor_sync(0xFFFFFFFFu, zq, o);
        ll += __shfl_xor_sync(0xFFFFFFFFu, ll, o);
    }

    float nz = sqrtf(zz), nq = sqrtf(qq);
    float iz = 1.f / (nz + EPSF), iq = 1.f / (nq + EPSF);
    float s2 = zz * iz * iz + 2.f * zq * iz * iq + qq * iq * iq;
    float A2 = 2.f * (zz * iz + zq * iq) / s2;
    float Bc = 2.f * zz * iz * iq;
    float cz = 1.f - A2 * iz;
    float cq = Bc - A2 * iq;
    float sc = nq * iz;

    float* op = out_q + (size_t)row * DD;
    ushort4* rh = (ushort4*)g_res_h4;
    ushort4* rl = (ushort4*)g_res_l4;
#pragma unroll
    for (int j = 0; j < 4; j++) {
        float4 z = zv[j], q = qv[j], t, r, o;
        t.x = (z.x * cz + q.x * cq) * sc;
        t.y = (z.y * cz + q.y * cq) * sc;
        t.z = (z.z * cz + q.z * cq) * sc;
        t.w = (z.w * cz + q.w * cq) * sc;
        r.x = z.x - t.x; r.y = z.y - t.y; r.z = z.z - t.z; r.w = z.w - t.w;
        ((float4*)zp)[lane + 32 * j] = r;
        o = ((float4*)op)[lane + 32 * j];
        o.x += t.x; o.y += t.y; o.z += t.z; o.w += t.w;
        ((float4*)op)[lane + 32 * j] = o;
        if (writeConv) {
            ushort4 h, l; split4(r, h, l);
            size_t e = (size_t)row * 128 + lane + 32 * j;
            rh[e] = h; rl[e] = l;
        }
    }

    if (writeIdx && lane == 0)
        out_if[(size_t)row * BQ + qi] = (float)idx;

    if (writeLoss) {
        if (lane == 0) ws[threadIdx.x >> 5] = ll;
        __syncthreads();
        if (threadIdx.x == 0) {
            float s = 0.f;
#pragma unroll
            for (int w = 0; w < 8; w++) s += ws[w];
            atomicAdd(&g_loss[qi], s);
        }
    }
}

// ---------------------------------------------------------------------------
__global__ void final_kernel(float* __restrict__ out_loss) {
    int i = threadIdx.x;
    if (i < BQ) out_loss[i] = g_loss[i] / (float)((size_t)MROWS * DD);
}

// ---------------------------------------------------------------------------
extern "C" void kernel_launch(void* const* d_in, const int* in_sizes, int n_in,
                              void* d_out, int out_size) {
    const float* x   = (const float*)d_in[0];
    const float* cbs = (const float*)d_in[1];
    if (n_in >= 2 && in_sizes[0] == BQ * CC * DD && in_sizes[1] == MROWS * DD) {
        const float* t = x; x = cbs; cbs = t;
    }

    float* out = (float*)d_out;
    const long long qElems = (long long)MROWS * DD;   // 16777216
    const long long iElems = (long long)MROWS * BQ;   // 262144
    float* out_q = out;
    float* out_i = out + qElems;
    float* out_l = out + qElems + iElems;
    int haveIdx  = (out_size >= qElems + iElems) ? 1 : 0;
    int haveLoss = (out_size >= qElems + iElems + BQ) ? 1 : 0;

    static int attrSet = 0;
    if (!attrSet) {
        cudaFuncSetAttribute(dist_mma_kernel,
                             cudaFuncAttributeMaxDynamicSharedMemorySize, SMEM_DYN);
        attrSet = 1;
    }

    init_kernel<<<1024, 256>>>(x, out_q);
    cbsq_kernel<<<BQ * CC / 8, 256>>>(cbs);

    for (int qi = 0; qi < BQ; qi++) {
        dist_mma_kernel<<<MROWS / 128, 256, SMEM_DYN>>>(qi);
        rotate_kernel<<<MROWS / 8, 256>>>(cbs, qi, out_q, out_i,
                                          haveIdx, haveLoss, qi < BQ - 1);
    }

    if (haveLoss) final_kernel<<<1, 32>>>(out_l);
}